// round 15
// baseline (speedup 1.0000x reference)
#include <cuda_runtime.h>

// SpatialTransformer: trilinear warp of vol[0] ([160,192,224,2] f32) by dense
// shift field trf[0] ([160,192,224,3] f32). Reference semantics: loc clipped,
// loc0=clip(floor), loc1=clip(loc0+1), w_c0=loc1-loc.
//
// Tile kernel v6: scaling tracks occupancy/issue (R12->R14: occ 40->59%,
// dur 113->97). This round: (1) TX=4, ZP=62 -> 58KB smem -> 4 blocks/SM
// (56 warps); (2) float-compare in-tile test + unclamped tile addressing
// (kills ~18 int-ALU ops/voxel; boundary-equal cases conservatively take the
// exact gmem fallback).

static constexpr int D0 = 160;
static constexpr int D1 = 192;
static constexpr int D2 = 224;

static constexpr int TX = 4, TY = 8, TZ = 56;      // output tile
static constexpr int H  = 2;                       // halo
static constexpr int HX = TX + 2 * H + 1;          // 9
static constexpr int HY = TY + 2 * H + 1;          // 13
static constexpr int HZ = TZ + 2 * H + 1;          // 61
static constexpr int ZP = 62;                      // padded z pitch (float2)
static constexpr int NTHREADS = TZ * TY;           // 448 (14 warps)
static constexpr int SMEM_BYTES = HX * HY * ZP * (int)sizeof(float2);  // 58032

__global__ __launch_bounds__(NTHREADS, 4) void st_warp_kernel(
    const float* __restrict__ vol,   // [D0,D1,D2,2]
    const float* __restrict__ trf,   // [D0,D1,D2,3]
    float2* __restrict__ out)        // [D0,D1,D2] of float2
{
    extern __shared__ float2 sv[];   // [HX*HY][ZP]

    const float2* __restrict__ v2 = (const float2*)vol;

    const int X0 = blockIdx.x * TX;
    const int Y0 = blockIdx.y * TY;
    const int Z0 = blockIdx.z * TZ;

    const int tid  = threadIdx.y * TZ + threadIdx.x;
    const int wid  = tid >> 5;
    const int lane = tid & 31;

    // ---- stage halo'd tile: one warp per row, lanes along z (coalesced) ----
    for (int r = wid; r < HX * HY; r += NTHREADS / 32) {
        int px = r / HY;
        int py = r - px * HY;
        int gx = min(max(X0 - H + px, 0), D0 - 1);
        int gy = min(max(Y0 - H + py, 0), D1 - 1);
        const float2* __restrict__ src = v2 + (gx * D1 + gy) * D2;
        float2* __restrict__ dst = sv + r * ZP;
        for (int pz = lane; pz < HZ; pz += 32) {
            int gz = min(max(Z0 - H + pz, 0), D2 - 1);
            dst[pz] = src[gz];
        }
    }

    const int z  = threadIdx.x;          // 0..55
    const int zg = Z0 + z;
    const int y  = Y0 + threadIdx.y;
    const int istep = D1 * D2;
    const int ibase = (X0 * D1 + y) * D2 + zg;

    const float mx = (float)(D0 - 1);
    const float my = (float)(D1 - 1);
    const float mz = (float)(D2 - 1);
    const int   bx = X0 - H, by = Y0 - H, bz = Z0 - H;  // tile origins
    // float tile bounds for the in-tile test:
    //   ok_d  <=>  l >= lo  &&  l < hi   (hi = origin + Hd - 1)
    // guarantees corner0 >= origin and corner1 <= origin + Hd - 1.
    const float xlo = (float)bx, xhi = (float)(bx + HX - 1);
    const float ylo = (float)by, yhi = (float)(by + HY - 1);
    const float zlo = (float)bz, zhi = (float)(bz + HZ - 1);
    const float xb = (float)X0;
    const float yf = (float)y;
    const float zf = (float)zg;

    // prefetch trf for xl=0 BEFORE the barrier (overlaps tile stage)
    float psx, psy, psz;
    {
        const float* t0 = trf + 3 * ibase;
        psx = __ldg(t0); psy = __ldg(t0 + 1); psz = __ldg(t0 + 2);
    }

    __syncthreads();

    #pragma unroll
    for (int xl = 0; xl < TX; xl++) {
        // prefetch next voxel's trf while this one computes
        float nsx, nsy, nsz;
        if (xl < TX - 1) {
            const float* t0 = trf + 3 * (ibase + (xl + 1) * istep);
            nsx = __ldg(t0); nsy = __ldg(t0 + 1); nsz = __ldg(t0 + 2);
        }

        float xf = xb + (float)xl;

        float lx = fminf(fmaxf(xf + psx, 0.0f), mx);
        float ly = fminf(fmaxf(yf + psy, 0.0f), my);
        float lz = fminf(fmaxf(zf + psz, 0.0f), mz);

        float fx0 = floorf(lx), fy0 = floorf(ly), fz0 = floorf(lz);
        float fx1 = fminf(fx0 + 1.0f, mx);
        float fy1 = fminf(fy0 + 1.0f, my);
        float fz1 = fminf(fz0 + 1.0f, mz);

        float wx0 = fx1 - lx, wx1 = 1.0f - wx0;
        float wy0 = fy1 - ly, wy1 = 1.0f - wy0;
        float wz0 = fz1 - lz, wz1 = 1.0f - wz0;

        int x0 = (int)fx0, x1 = (int)fx1;
        int y0 = (int)fy0, y1 = (int)fy1;
        int z0 = (int)fz0, z1 = (int)fz1;

        // float in-tile test (conservative at the upper edge)
        bool ok = (lx >= xlo) & (lx < xhi) &
                  (ly >= ylo) & (ly < yhi) &
                  (lz >= zlo) & (lz < zhi);

        float2 c000, c001, c010, c011, c100, c101, c110, c111;
        if (ok) {
            // unclamped tile coords; x1-x0 etc. handle volume-edge collapse
            int tix = x0 - bx;
            int tiy = y0 - by;
            int tiz = z0 - bz;
            int dX = (x1 - x0) * (HY * ZP);
            int dY = (y1 - y0) * ZP;
            int dz = z1 - z0;
            const float2* p = sv + (tix * HY + tiy) * ZP + tiz;
            c000 = p[0];            c001 = p[dz];
            c010 = p[dY];           c011 = p[dY + dz];
            c100 = p[dX];           c101 = p[dX + dz];
            c110 = p[dX + dY];      c111 = p[dX + dY + dz];
        } else {   // rare: exact gmem corners
            int gx0 = x0 * D1, gx1 = x1 * D1;
            int r00 = (gx0 + y0) * D2;
            int r01 = (gx0 + y1) * D2;
            int r10 = (gx1 + y0) * D2;
            int r11 = (gx1 + y1) * D2;
            c000 = __ldg(&v2[r00 + z0]);  c001 = __ldg(&v2[r00 + z1]);
            c010 = __ldg(&v2[r01 + z0]);  c011 = __ldg(&v2[r01 + z1]);
            c100 = __ldg(&v2[r10 + z0]);  c101 = __ldg(&v2[r10 + z1]);
            c110 = __ldg(&v2[r11 + z0]);  c111 = __ldg(&v2[r11 + z1]);
        }

        // nested lerp: z, then y, then x
        float a00x = wz0 * c000.x + wz1 * c001.x;
        float a00y = wz0 * c000.y + wz1 * c001.y;
        float a01x = wz0 * c010.x + wz1 * c011.x;
        float a01y = wz0 * c010.y + wz1 * c011.y;
        float a10x = wz0 * c100.x + wz1 * c101.x;
        float a10y = wz0 * c100.y + wz1 * c101.y;
        float a11x = wz0 * c110.x + wz1 * c111.x;
        float a11y = wz0 * c110.y + wz1 * c111.y;

        float b0x = wy0 * a00x + wy1 * a01x;
        float b0y = wy0 * a00y + wy1 * a01y;
        float b1x = wy0 * a10x + wy1 * a11x;
        float b1y = wy0 * a10y + wy1 * a11y;

        float2 o;
        o.x = wx0 * b0x + wx1 * b1x;
        o.y = wx0 * b0y + wx1 * b1y;
        out[ibase + xl * istep] = o;

        psx = nsx; psy = nsy; psz = nsz;
    }
}

extern "C" void kernel_launch(void* const* d_in, const int* in_sizes, int n_in,
                              void* d_out, int out_size)
{
    const float* vol = (const float*)d_in[0];   // [2,160,192,224,2]; batch 0 at base
    const float* trf = (const float*)d_in[1];   // [2,160,192,224,3]; batch 0 at base
    float2* out = (float2*)d_out;               // [160,192,224,2]

    cudaFuncSetAttribute(st_warp_kernel,
                         cudaFuncAttributeMaxDynamicSharedMemorySize, SMEM_BYTES);

    dim3 block(TZ, TY, 1);                  // 56 x 8 = 448 threads
    dim3 grid(D0 / TX, D1 / TY, D2 / TZ);   // 40 x 24 x 4
    st_warp_kernel<<<grid, block, SMEM_BYTES>>>(vol, trf, out);
}

// round 16
// speedup vs baseline: 1.2299x; 1.2299x over previous
#include <cuda_runtime.h>

// SpatialTransformer: trilinear warp of vol[0] ([160,192,224,2] f32) by dense
// shift field trf[0] ([160,192,224,3] f32). Reference semantics: loc clipped,
// loc0=clip(floor), loc1=clip(loc0+1), w_c0=loc1-loc.
//
// Direct-gather v2 (tile track closed at R15). R4 baseline was L1tex
// wavefront-bound at 91% with only 8 outstanding gathers/thread. This
// version: one block = 2 adjacent z-rows, 224 threads, 2 voxels/thread ->
// 16 independent gathers in flight per warp (double MLP), same math.

static constexpr int D0 = 160;
static constexpr int D1 = 192;
static constexpr int D2 = 224;

__global__ __launch_bounds__(D2, 5) void st_warp_kernel(
    const float* __restrict__ vol,   // [D0,D1,D2,2]
    const float* __restrict__ trf,   // [D0,D1,D2,3]
    float2* __restrict__ out)        // [D0,D1,D2] of float2 (2 channels)
{
    const float2* __restrict__ v2 = (const float2*)vol;

    int z    = threadIdx.x;              // 0..223
    int row0 = blockIdx.x * 2;           // first of 2 rows
    const float mx = (float)(D0 - 1);
    const float my = (float)(D1 - 1);
    const float mz = (float)(D2 - 1);

    // ---- per-voxel state for both rows ----
    float wx0[2], wx1[2], wy0[2], wy1[2], wz0[2], wz1[2];
    int   r00[2], r01[2], r10[2], r11[2], zz0[2], zz1[2];
    int   idx[2];

    #pragma unroll
    for (int v = 0; v < 2; v++) {
        int row = row0 + v;
        int y = row % D1;
        int x = row / D1;
        int i = row * D2 + z;
        idx[v] = i;

        float sx = __ldg(&trf[3 * i + 0]);
        float sy = __ldg(&trf[3 * i + 1]);
        float sz = __ldg(&trf[3 * i + 2]);

        float lx = fminf(fmaxf((float)x + sx, 0.0f), mx);
        float ly = fminf(fmaxf((float)y + sy, 0.0f), my);
        float lz = fminf(fmaxf((float)z + sz, 0.0f), mz);

        float fx0 = floorf(lx), fy0 = floorf(ly), fz0 = floorf(lz);
        float fx1 = fminf(fx0 + 1.0f, mx);
        float fy1 = fminf(fy0 + 1.0f, my);
        float fz1 = fminf(fz0 + 1.0f, mz);

        wx0[v] = fx1 - lx;  wx1[v] = 1.0f - wx0[v];
        wy0[v] = fy1 - ly;  wy1[v] = 1.0f - wy0[v];
        wz0[v] = fz1 - lz;  wz1[v] = 1.0f - wz0[v];

        int x0 = (int)fx0, x1 = (int)fx1;
        int y0 = (int)fy0, y1 = (int)fy1;
        zz0[v] = (int)fz0;  zz1[v] = (int)fz1;

        int bx0 = x0 * D1;
        int bx1 = x1 * D1;
        r00[v] = (bx0 + y0) * D2;
        r01[v] = (bx0 + y1) * D2;
        r10[v] = (bx1 + y0) * D2;
        r11[v] = (bx1 + y1) * D2;
    }

    // ---- issue all 16 gathers back-to-back (max MLP) ----
    float2 c[2][8];
    #pragma unroll
    for (int v = 0; v < 2; v++) {
        c[v][0] = __ldg(&v2[r00[v] + zz0[v]]);
        c[v][1] = __ldg(&v2[r00[v] + zz1[v]]);
        c[v][2] = __ldg(&v2[r01[v] + zz0[v]]);
        c[v][3] = __ldg(&v2[r01[v] + zz1[v]]);
        c[v][4] = __ldg(&v2[r10[v] + zz0[v]]);
        c[v][5] = __ldg(&v2[r10[v] + zz1[v]]);
        c[v][6] = __ldg(&v2[r11[v] + zz0[v]]);
        c[v][7] = __ldg(&v2[r11[v] + zz1[v]]);
    }

    // ---- lerp trees + stores ----
    #pragma unroll
    for (int v = 0; v < 2; v++) {
        float a00x = wz0[v] * c[v][0].x + wz1[v] * c[v][1].x;
        float a00y = wz0[v] * c[v][0].y + wz1[v] * c[v][1].y;
        float a01x = wz0[v] * c[v][2].x + wz1[v] * c[v][3].x;
        float a01y = wz0[v] * c[v][2].y + wz1[v] * c[v][3].y;
        float a10x = wz0[v] * c[v][4].x + wz1[v] * c[v][5].x;
        float a10y = wz0[v] * c[v][4].y + wz1[v] * c[v][5].y;
        float a11x = wz0[v] * c[v][6].x + wz1[v] * c[v][7].x;
        float a11y = wz0[v] * c[v][6].y + wz1[v] * c[v][7].y;

        float b0x = wy0[v] * a00x + wy1[v] * a01x;
        float b0y = wy0[v] * a00y + wy1[v] * a01y;
        float b1x = wy0[v] * a10x + wy1[v] * a11x;
        float b1y = wy0[v] * a10y + wy1[v] * a11y;

        float2 o;
        o.x = wx0[v] * b0x + wx1[v] * b1x;
        o.y = wx0[v] * b0y + wx1[v] * b1y;
        out[idx[v]] = o;
    }
}

extern "C" void kernel_launch(void* const* d_in, const int* in_sizes, int n_in,
                              void* d_out, int out_size)
{
    const float* vol = (const float*)d_in[0];   // [2,160,192,224,2]; batch 0 at base
    const float* trf = (const float*)d_in[1];   // [2,160,192,224,3]; batch 0 at base
    float2* out = (float2*)d_out;               // [160,192,224,2]

    st_warp_kernel<<<(D0 * D1) / 2, D2>>>(vol, trf, out);   // 15360 blocks
}